// round 5
// baseline (speedup 1.0000x reference)
#include <cuda_runtime.h>
#include <cstdint>

// YOLO detection decode: x (64, 255, 52, 52) f32 -> out (64, 8112, 85) f32
// v5: channel-major smem tile [85 ch][52 pos] with SW128 swizzle.
//   Phase 1: coalesced float4 LDG -> transform -> ONE STS.128 at 16B-unit j
//            (consecutive lanes -> consecutive units -> conflict-free).
//   Phase 2: per output float4, 4 scalar LDS (swizzle spreads the stride-52-unit
//            lane pattern over ~8 bank groups) -> contiguous float4 STG.

#define G 52
#define GG 2704              // G*G
#define GGV 676              // GG/4 (channel stride in float4)
#define IN_PER_B 689520      // 255*GG
#define NE 85
#define TILE 52
#define QV 13                // TILE/4
#define NV (NE * QV)         // 1105 float4 per tile (= 16B units in smem)
#define TILES_PER_PLANE 52
#define THREADS 256
#define SMEM_BYTES 17792     // 85*52*4 = 17680 -> pad to 128B multiple

#define SWZ(b) ((b) ^ (((b) >> 3) & 0x70))

__constant__ float c_aw[3] = {10.0f, 16.0f, 33.0f};
__constant__ float c_ah[3] = {13.0f, 30.0f, 23.0f};

__device__ __forceinline__ float fsigmoid(float v) {
    return __fdividef(1.0f, 1.0f + __expf(-v));
}

__global__ __launch_bounds__(THREADS, 8)
void det_decode_kernel(const float* __restrict__ x, float* __restrict__ out) {
    __shared__ alignas(128) char smem[SMEM_BYTES];

    // Tile -> (b, a, p0). tiles/anchor = 52, tiles/batch = 156.
    const int t   = blockIdx.x;
    const int b   = t / 156;
    const int rem = t - b * 156;
    const int a   = rem / TILES_PER_PLANE;
    const int pt  = rem - a * TILES_PER_PLANE;
    const int p0  = pt * TILE;

    const float4* __restrict__ src = reinterpret_cast<const float4*>(
        x + (size_t)b * IN_PER_B + (size_t)(a * NE) * GG + p0);

    const float aw = c_aw[a];
    const float ah = c_ah[a];

    // Phase 1: load-transform-store. Logical layout: channel-major,
    // word = e*52 + p. Thread j's float4 = channel e, rows 4q..4q+3
    // = logical words 4j..4j+3 = 16B unit j.  (j = e*13 + q)
    #pragma unroll 4
    for (int j = threadIdx.x; j < NV; j += THREADS) {
        const int e = j / QV;
        const int q = j - e * QV;
        const float4 v = __ldcs(src + e * GGV + q);
        const int lp = q * 4;

        float4 o;
        if (e >= 4) {
            o.x = fsigmoid(v.x); o.y = fsigmoid(v.y);
            o.z = fsigmoid(v.z); o.w = fsigmoid(v.w);
        } else if (e == 0) {
            const int p = p0 + lp;
            o.x = (fsigmoid(v.x) + (float)((p    ) % G)) * 8.0f;
            o.y = (fsigmoid(v.y) + (float)((p + 1) % G)) * 8.0f;
            o.z = (fsigmoid(v.z) + (float)((p + 2) % G)) * 8.0f;
            o.w = (fsigmoid(v.w) + (float)((p + 3) % G)) * 8.0f;
        } else if (e == 1) {
            const int p = p0 + lp;
            o.x = (fsigmoid(v.x) + (float)((p    ) / G)) * 8.0f;
            o.y = (fsigmoid(v.y) + (float)((p + 1) / G)) * 8.0f;
            o.z = (fsigmoid(v.z) + (float)((p + 2) / G)) * 8.0f;
            o.w = (fsigmoid(v.w) + (float)((p + 3) / G)) * 8.0f;
        } else if (e == 2) {
            o.x = __expf(v.x) * aw; o.y = __expf(v.y) * aw;
            o.z = __expf(v.z) * aw; o.w = __expf(v.w) * aw;
        } else { // e == 3
            o.x = __expf(v.x) * ah; o.y = __expf(v.y) * ah;
            o.z = __expf(v.z) * ah; o.w = __expf(v.w) * ah;
        }

        *reinterpret_cast<float4*>(smem + SWZ((uint32_t)j << 4)) = o;
    }

    __syncthreads();

    // Phase 2: output word w = lp*85 + e  <->  smem logical word e*52 + lp.
    // Each thread builds one output float4 from 4 swizzled scalar LDS.
    float4* __restrict__ dst =
        reinterpret_cast<float4*>(out + (size_t)t * (TILE * NE));
    #pragma unroll 4
    for (int j = threadIdx.x; j < NV; j += THREADS) {
        const int w0 = 4 * j;
        const int lp0 = w0 / NE;
        const int e0  = w0 - lp0 * NE;

        int e1 = e0 + 1, l1 = lp0; if (e1 >= NE) { e1 = 0; l1++; }
        int e2 = e1 + 1, l2 = l1;  if (e2 >= NE) { e2 = 0; l2++; }
        int e3 = e2 + 1, l3 = l2;  if (e3 >= NE) { e3 = 0; l3++; }

        float4 o;
        o.x = *reinterpret_cast<const float*>(smem + SWZ((uint32_t)(e0 * TILE + lp0) << 2));
        o.y = *reinterpret_cast<const float*>(smem + SWZ((uint32_t)(e1 * TILE + l1 ) << 2));
        o.z = *reinterpret_cast<const float*>(smem + SWZ((uint32_t)(e2 * TILE + l2 ) << 2));
        o.w = *reinterpret_cast<const float*>(smem + SWZ((uint32_t)(e3 * TILE + l3 ) << 2));

        __stcs(dst + j, o);
    }
}

extern "C" void kernel_launch(void* const* d_in, const int* in_sizes, int n_in,
                              void* d_out, int out_size) {
    const float* x = (const float*)d_in[0];
    float* out = (float*)d_out;
    const int blocks = out_size / (TILE * NE);   // 9984
    det_decode_kernel<<<blocks, THREADS>>>(x, out);
}

// round 6
// speedup vs baseline: 1.0814x; 1.0814x over previous
#include <cuda_runtime.h>
#include <cstdint>

// YOLO detection decode: x (64, 255, 52, 52) f32 -> out (64, 8112, 85) f32
// v6 = v3 phase-1 (known good) + TMA bulk store phase-2.
//   Phase 1: coalesced float4 LDG per channel, transform, scalar-STS transpose
//            into smem in OUTPUT layout (word = lp*85 + e).
//   Phase 2: smem tile is the tile's contiguous 17680B output span ->
//            single cp.async.bulk.global.shared::cta from one thread.
//            Removes all LDS + STG + loop issue from the SM instruction stream.

#define G 52
#define GG 2704              // G*G
#define GGV 676              // GG/4 (channel stride in float4)
#define IN_PER_B 689520      // 255*GG
#define NE 85
#define TILE 52
#define QV 13                // TILE/4
#define NV (NE * QV)         // 1105 float4 per tile
#define TILES_PER_PLANE 52
#define THREADS 256
#define TILE_BYTES (TILE * NE * 4)   // 17680

__constant__ float c_aw[3] = {10.0f, 16.0f, 33.0f};
__constant__ float c_ah[3] = {13.0f, 30.0f, 23.0f};

__device__ __forceinline__ float fsigmoid(float v) {
    return __fdividef(1.0f, 1.0f + __expf(-v));
}

__global__ __launch_bounds__(THREADS, 8)
void det_decode_kernel(const float* __restrict__ x, float* __restrict__ out) {
    __shared__ alignas(128) float s[TILE * NE];

    // Tile -> (b, a, p0). tiles/anchor = 52, tiles/batch = 156.
    const int t   = blockIdx.x;
    const int b   = t / 156;
    const int rem = t - b * 156;
    const int a   = rem / TILES_PER_PLANE;
    const int pt  = rem - a * TILES_PER_PLANE;
    const int p0  = pt * TILE;

    const float4* __restrict__ src = reinterpret_cast<const float4*>(
        x + (size_t)b * IN_PER_B + (size_t)(a * NE) * GG + p0);

    const float aw = c_aw[a];
    const float ah = c_ah[a];

    // Phase 1: load-transform-stage (identical to v3).
    #pragma unroll 4
    for (int j = threadIdx.x; j < NV; j += THREADS) {
        const int e = j / QV;            // channel 0..84
        const int q = j - e * QV;        // float4 index within channel
        const float4 v = __ldcs(src + e * GGV + q);
        const int lp = q * 4;            // local row of component .x

        float o0, o1, o2, o3;
        if (e >= 4) {
            o0 = fsigmoid(v.x); o1 = fsigmoid(v.y);
            o2 = fsigmoid(v.z); o3 = fsigmoid(v.w);
        } else if (e == 0) {
            const int p = p0 + lp;
            o0 = (fsigmoid(v.x) + (float)((p    ) % G)) * 8.0f;
            o1 = (fsigmoid(v.y) + (float)((p + 1) % G)) * 8.0f;
            o2 = (fsigmoid(v.z) + (float)((p + 2) % G)) * 8.0f;
            o3 = (fsigmoid(v.w) + (float)((p + 3) % G)) * 8.0f;
        } else if (e == 1) {
            const int p = p0 + lp;
            o0 = (fsigmoid(v.x) + (float)((p    ) / G)) * 8.0f;
            o1 = (fsigmoid(v.y) + (float)((p + 1) / G)) * 8.0f;
            o2 = (fsigmoid(v.z) + (float)((p + 2) / G)) * 8.0f;
            o3 = (fsigmoid(v.w) + (float)((p + 3) / G)) * 8.0f;
        } else if (e == 2) {
            o0 = __expf(v.x) * aw; o1 = __expf(v.y) * aw;
            o2 = __expf(v.z) * aw; o3 = __expf(v.w) * aw;
        } else { // e == 3
            o0 = __expf(v.x) * ah; o1 = __expf(v.y) * ah;
            o2 = __expf(v.z) * ah; o3 = __expf(v.w) * ah;
        }
        float* sp = s + lp * NE + e;     // output layout: word = lp*85 + e
        sp[0 * NE] = o0; sp[1 * NE] = o1; sp[2 * NE] = o2; sp[3 * NE] = o3;
    }

    __syncthreads();

    // Phase 2: one bulk async copy smem -> gmem (contiguous 17680B span).
    if (threadIdx.x == 0) {
        uint32_t saddr;
        asm volatile("{ .reg .u64 t; cvta.to.shared.u64 t, %1; cvt.u32.u64 %0, t; }"
                     : "=r"(saddr) : "l"(s));
        float* gdst = out + (size_t)t * (TILE * NE);
        asm volatile("fence.proxy.async.shared::cta;" ::: "memory");
        asm volatile("cp.async.bulk.global.shared::cta.bulk_group [%0], [%1], %2;"
                     :: "l"(gdst), "r"(saddr), "r"((uint32_t)TILE_BYTES) : "memory");
        asm volatile("cp.async.bulk.commit_group;" ::: "memory");
        // Must complete before CTA exit reclaims smem.
        asm volatile("cp.async.bulk.wait_group 0;" ::: "memory");
    }
}

extern "C" void kernel_launch(void* const* d_in, const int* in_sizes, int n_in,
                              void* d_out, int out_size) {
    const float* x = (const float*)d_in[0];
    float* out = (float*)d_out;
    const int blocks = out_size / (TILE * NE);   // 9984
    det_decode_kernel<<<blocks, THREADS>>>(x, out);
}

// round 7
// speedup vs baseline: 1.0854x; 1.0036x over previous
#include <cuda_runtime.h>
#include <cstdint>

// YOLO detection decode: x (64, 255, 52, 52) f32 -> out (64, 8112, 85) f32
// v7 = v6 with cp.async.bulk.wait_group.READ (block only until smem source is
//      read; global writes drain in background -> fast CTA retirement).
//   Phase 1: coalesced float4 LDG per channel, transform, scalar-STS transpose
//            into smem in OUTPUT layout (word = lp*85 + e).
//   Phase 2: single cp.async.bulk.global.shared::cta of the contiguous
//            17680B output span, issued by one thread.

#define G 52
#define GG 2704              // G*G
#define GGV 676              // GG/4 (channel stride in float4)
#define IN_PER_B 689520      // 255*GG
#define NE 85
#define TILE 52
#define QV 13                // TILE/4
#define NV (NE * QV)         // 1105 float4 per tile
#define TILES_PER_PLANE 52
#define THREADS 256
#define TILE_BYTES (TILE * NE * 4)   // 17680

__constant__ float c_aw[3] = {10.0f, 16.0f, 33.0f};
__constant__ float c_ah[3] = {13.0f, 30.0f, 23.0f};

__device__ __forceinline__ float fsigmoid(float v) {
    return __fdividef(1.0f, 1.0f + __expf(-v));
}

__global__ __launch_bounds__(THREADS, 8)
void det_decode_kernel(const float* __restrict__ x, float* __restrict__ out) {
    __shared__ alignas(128) float s[TILE * NE];

    // Tile -> (b, a, p0). tiles/anchor = 52, tiles/batch = 156.
    const int t   = blockIdx.x;
    const int b   = t / 156;
    const int rem = t - b * 156;
    const int a   = rem / TILES_PER_PLANE;
    const int pt  = rem - a * TILES_PER_PLANE;
    const int p0  = pt * TILE;

    const float4* __restrict__ src = reinterpret_cast<const float4*>(
        x + (size_t)b * IN_PER_B + (size_t)(a * NE) * GG + p0);

    const float aw = c_aw[a];
    const float ah = c_ah[a];

    // Phase 1: load-transform-stage.
    #pragma unroll 4
    for (int j = threadIdx.x; j < NV; j += THREADS) {
        const int e = j / QV;            // channel 0..84
        const int q = j - e * QV;        // float4 index within channel
        const float4 v = __ldcs(src + e * GGV + q);
        const int lp = q * 4;            // local row of component .x

        float o0, o1, o2, o3;
        if (e >= 4) {
            o0 = fsigmoid(v.x); o1 = fsigmoid(v.y);
            o2 = fsigmoid(v.z); o3 = fsigmoid(v.w);
        } else if (e == 0) {
            const int p = p0 + lp;
            o0 = (fsigmoid(v.x) + (float)((p    ) % G)) * 8.0f;
            o1 = (fsigmoid(v.y) + (float)((p + 1) % G)) * 8.0f;
            o2 = (fsigmoid(v.z) + (float)((p + 2) % G)) * 8.0f;
            o3 = (fsigmoid(v.w) + (float)((p + 3) % G)) * 8.0f;
        } else if (e == 1) {
            const int p = p0 + lp;
            o0 = (fsigmoid(v.x) + (float)((p    ) / G)) * 8.0f;
            o1 = (fsigmoid(v.y) + (float)((p + 1) / G)) * 8.0f;
            o2 = (fsigmoid(v.z) + (float)((p + 2) / G)) * 8.0f;
            o3 = (fsigmoid(v.w) + (float)((p + 3) / G)) * 8.0f;
        } else if (e == 2) {
            o0 = __expf(v.x) * aw; o1 = __expf(v.y) * aw;
            o2 = __expf(v.z) * aw; o3 = __expf(v.w) * aw;
        } else { // e == 3
            o0 = __expf(v.x) * ah; o1 = __expf(v.y) * ah;
            o2 = __expf(v.z) * ah; o3 = __expf(v.w) * ah;
        }
        float* sp = s + lp * NE + e;     // output layout: word = lp*85 + e
        sp[0 * NE] = o0; sp[1 * NE] = o1; sp[2 * NE] = o2; sp[3 * NE] = o3;
    }

    __syncthreads();

    // Phase 2: one bulk async copy smem -> gmem (contiguous 17680B span).
    // wait_group.read: only wait until the smem SOURCE has been read (safe to
    // reclaim smem at CTA exit); global writes complete asynchronously.
    if (threadIdx.x == 0) {
        uint32_t saddr;
        asm volatile("{ .reg .u64 t; cvta.to.shared.u64 t, %1; cvt.u32.u64 %0, t; }"
                     : "=r"(saddr) : "l"(s));
        float* gdst = out + (size_t)t * (TILE * NE);
        asm volatile("fence.proxy.async.shared::cta;" ::: "memory");
        asm volatile("cp.async.bulk.global.shared::cta.bulk_group [%0], [%1], %2;"
                     :: "l"(gdst), "r"(saddr), "r"((uint32_t)TILE_BYTES) : "memory");
        asm volatile("cp.async.bulk.commit_group;" ::: "memory");
        asm volatile("cp.async.bulk.wait_group.read 0;" ::: "memory");
    }
}

extern "C" void kernel_launch(void* const* d_in, const int* in_sizes, int n_in,
                              void* d_out, int out_size) {
    const float* x = (const float*)d_in[0];
    float* out = (float*)d_out;
    const int blocks = out_size / (TILE * NE);   // 9984
    det_decode_kernel<<<blocks, THREADS>>>(x, out);
}

// round 8
// speedup vs baseline: 1.1144x; 1.0267x over previous
#include <cuda_runtime.h>
#include <cstdint>

// YOLO detection decode: x (64, 255, 52, 52) f32 -> out (64, 8112, 85) f32
// v8 = v3 (best bench: 59.6us) + tanh.approx-based sigmoid (1 MUFU instead of 2).
//   sigmoid(v) = 0.5 + 0.5*tanh(0.5*v)  -- MUFU.TANH, halves MUFU pressure.
//   Phase 1: coalesced float4 LDG per channel, transform, scalar-STS transpose
//            into smem in output layout (word = lp*85 + e), ~2-way conflicts.
//   Phase 2: contiguous 4420-float span stored as float4 (streaming STG).

#define G 52
#define GG 2704              // G*G
#define GGV 676              // GG/4 (channel stride in float4)
#define IN_PER_B 689520      // 255*GG
#define NE 85
#define TILE 52
#define QV 13                // TILE/4
#define NV (NE * QV)         // 1105 float4 per tile
#define TILES_PER_PLANE 52
#define THREADS 256

__constant__ float c_aw[3] = {10.0f, 16.0f, 33.0f};
__constant__ float c_ah[3] = {13.0f, 30.0f, 23.0f};

__device__ __forceinline__ float fsigmoid(float v) {
    // sigmoid(v) = 0.5 + 0.5*tanh(0.5*v); MUFU.TANH, abs err ~2^-12
    float t;
    asm("tanh.approx.f32 %0, %1;" : "=f"(t) : "f"(0.5f * v));
    return fmaf(0.5f, t, 0.5f);
}

__global__ __launch_bounds__(THREADS, 8)
void det_decode_kernel(const float* __restrict__ x, float* __restrict__ out) {
    __shared__ alignas(128) float s[TILE * NE];   // 17,680 B

    // Tile -> (b, a, p0). tiles/anchor = 52, tiles/batch = 156.
    const int t   = blockIdx.x;
    const int b   = t / 156;
    const int rem = t - b * 156;
    const int a   = rem / TILES_PER_PLANE;
    const int pt  = rem - a * TILES_PER_PLANE;
    const int p0  = pt * TILE;

    const float4* __restrict__ src = reinterpret_cast<const float4*>(
        x + (size_t)b * IN_PER_B + (size_t)(a * NE) * GG + p0);

    const float aw = c_aw[a];
    const float ah = c_ah[a];

    // Phase 1: load-transform-stage.
    #pragma unroll 4
    for (int j = threadIdx.x; j < NV; j += THREADS) {
        const int e = j / QV;            // channel 0..84
        const int q = j - e * QV;        // float4 index within channel
        const float4 v = __ldcs(src + e * GGV + q);
        const int lp = q * 4;            // local row of component .x

        float o0, o1, o2, o3;
        if (e >= 4) {
            o0 = fsigmoid(v.x); o1 = fsigmoid(v.y);
            o2 = fsigmoid(v.z); o3 = fsigmoid(v.w);
        } else if (e == 0) {
            const int p = p0 + lp;
            o0 = (fsigmoid(v.x) + (float)((p    ) % G)) * 8.0f;
            o1 = (fsigmoid(v.y) + (float)((p + 1) % G)) * 8.0f;
            o2 = (fsigmoid(v.z) + (float)((p + 2) % G)) * 8.0f;
            o3 = (fsigmoid(v.w) + (float)((p + 3) % G)) * 8.0f;
        } else if (e == 1) {
            const int p = p0 + lp;
            o0 = (fsigmoid(v.x) + (float)((p    ) / G)) * 8.0f;
            o1 = (fsigmoid(v.y) + (float)((p + 1) / G)) * 8.0f;
            o2 = (fsigmoid(v.z) + (float)((p + 2) / G)) * 8.0f;
            o3 = (fsigmoid(v.w) + (float)((p + 3) / G)) * 8.0f;
        } else if (e == 2) {
            o0 = __expf(v.x) * aw; o1 = __expf(v.y) * aw;
            o2 = __expf(v.z) * aw; o3 = __expf(v.w) * aw;
        } else { // e == 3
            o0 = __expf(v.x) * ah; o1 = __expf(v.y) * ah;
            o2 = __expf(v.z) * ah; o3 = __expf(v.w) * ah;
        }
        float* sp = s + lp * NE + e;     // output layout: word = lp*85 + e
        sp[0 * NE] = o0; sp[1 * NE] = o1; sp[2 * NE] = o2; sp[3 * NE] = o3;
    }

    __syncthreads();

    // Phase 2: tile's output is one contiguous span of TILE*NE = 4420 floats.
    float4* __restrict__ dst =
        reinterpret_cast<float4*>(out + (size_t)t * (TILE * NE));
    const float4* __restrict__ ss = reinterpret_cast<const float4*>(s);
    #pragma unroll 4
    for (int j = threadIdx.x; j < NV; j += THREADS) {
        __stcs(dst + j, ss[j]);
    }
}

extern "C" void kernel_launch(void* const* d_in, const int* in_sizes, int n_in,
                              void* d_out, int out_size) {
    const float* x = (const float*)d_in[0];
    float* out = (float*)d_out;
    const int blocks = out_size / (TILE * NE);   // 9984
    det_decode_kernel<<<blocks, THREADS>>>(x, out);
}

// round 9
// speedup vs baseline: 1.1901x; 1.0679x over previous
#include <cuda_runtime.h>
#include <cstdint>

// YOLO detection decode: x (64, 255, 52, 52) f32 -> out (64, 8112, 85) f32
// v9 = v8 with:
//  - default-cached loads (no __ldcs): tile-boundary 32B sectors are shared by
//    adjacent blocks; evict-first was forcing ~8% re-read from DRAM.
//  - explicit load batching: each thread issues its 4 (+1 predicated) LDG.128
//    back-to-back before any transform -> guaranteed MLP, no tail loop.
//  Phase 1: coalesced float4 LDG per channel, transform (tanh-sigmoid),
//           scalar-STS transpose into smem in output layout (word = lp*85+e).
//  Phase 2: contiguous 4420-float span stored as float4 (streaming STG).

#define G 52
#define GG 2704              // G*G
#define GGV 676              // GG/4 (channel stride in float4)
#define IN_PER_B 689520      // 255*GG
#define NE 85
#define TILE 52
#define QV 13                // TILE/4
#define NV (NE * QV)         // 1105 float4 per tile
#define TILES_PER_PLANE 52
#define THREADS 256

__constant__ float c_aw[3] = {10.0f, 16.0f, 33.0f};
__constant__ float c_ah[3] = {13.0f, 30.0f, 23.0f};

__device__ __forceinline__ float fsigmoid(float v) {
    // sigmoid(v) = 0.5 + 0.5*tanh(0.5*v); MUFU.TANH, abs err ~2^-12
    float t;
    asm("tanh.approx.f32 %0, %1;" : "=f"(t) : "f"(0.5f * v));
    return fmaf(0.5f, t, 0.5f);
}

__device__ __forceinline__ void transform_store(
    float* __restrict__ s, float4 v, int j, int p0, float aw, float ah) {
    const int e = j / QV;
    const int q = j - e * QV;
    const int lp = q * 4;

    float o0, o1, o2, o3;
    if (e >= 4) {
        o0 = fsigmoid(v.x); o1 = fsigmoid(v.y);
        o2 = fsigmoid(v.z); o3 = fsigmoid(v.w);
    } else if (e == 0) {
        const int p = p0 + lp;
        o0 = (fsigmoid(v.x) + (float)((p    ) % G)) * 8.0f;
        o1 = (fsigmoid(v.y) + (float)((p + 1) % G)) * 8.0f;
        o2 = (fsigmoid(v.z) + (float)((p + 2) % G)) * 8.0f;
        o3 = (fsigmoid(v.w) + (float)((p + 3) % G)) * 8.0f;
    } else if (e == 1) {
        const int p = p0 + lp;
        o0 = (fsigmoid(v.x) + (float)((p    ) / G)) * 8.0f;
        o1 = (fsigmoid(v.y) + (float)((p + 1) / G)) * 8.0f;
        o2 = (fsigmoid(v.z) + (float)((p + 2) / G)) * 8.0f;
        o3 = (fsigmoid(v.w) + (float)((p + 3) / G)) * 8.0f;
    } else if (e == 2) {
        o0 = __expf(v.x) * aw; o1 = __expf(v.y) * aw;
        o2 = __expf(v.z) * aw; o3 = __expf(v.w) * aw;
    } else { // e == 3
        o0 = __expf(v.x) * ah; o1 = __expf(v.y) * ah;
        o2 = __expf(v.z) * ah; o3 = __expf(v.w) * ah;
    }
    float* sp = s + lp * NE + e;     // output layout: word = lp*85 + e
    sp[0 * NE] = o0; sp[1 * NE] = o1; sp[2 * NE] = o2; sp[3 * NE] = o3;
}

__global__ __launch_bounds__(THREADS, 8)
void det_decode_kernel(const float* __restrict__ x, float* __restrict__ out) {
    __shared__ alignas(128) float s[TILE * NE];   // 17,680 B

    // Tile -> (b, a, p0). tiles/anchor = 52, tiles/batch = 156.
    const int t   = blockIdx.x;
    const int b   = t / 156;
    const int rem = t - b * 156;
    const int a   = rem / TILES_PER_PLANE;
    const int pt  = rem - a * TILES_PER_PLANE;
    const int p0  = pt * TILE;

    const float4* __restrict__ src = reinterpret_cast<const float4*>(
        x + (size_t)b * IN_PER_B + (size_t)(a * NE) * GG + p0);

    const float aw = c_aw[a];
    const float ah = c_ah[a];

    const int tid = threadIdx.x;
    const int j0 = tid;
    const int j1 = tid + THREADS;
    const int j2 = tid + 2 * THREADS;
    const int j3 = tid + 3 * THREADS;
    const int j4 = tid + 4 * THREADS;          // valid only for tid < 81
    const bool tail = (j4 < NV);

    // Issue all loads back-to-back (MLP = 5 per thread).
    #define SRCIDX(j) ((j) / QV * GGV + ((j) - (j) / QV * QV))
    const float4 v0 = src[SRCIDX(j0)];
    const float4 v1 = src[SRCIDX(j1)];
    const float4 v2 = src[SRCIDX(j2)];
    const float4 v3 = src[SRCIDX(j3)];
    float4 v4 = make_float4(0.f, 0.f, 0.f, 0.f);
    if (tail) v4 = src[SRCIDX(j4)];
    #undef SRCIDX

    transform_store(s, v0, j0, p0, aw, ah);
    transform_store(s, v1, j1, p0, aw, ah);
    transform_store(s, v2, j2, p0, aw, ah);
    transform_store(s, v3, j3, p0, aw, ah);
    if (tail) transform_store(s, v4, j4, p0, aw, ah);

    __syncthreads();

    // Phase 2: tile's output is one contiguous span of TILE*NE = 4420 floats.
    float4* __restrict__ dst =
        reinterpret_cast<float4*>(out + (size_t)t * (TILE * NE));
    const float4* __restrict__ ss = reinterpret_cast<const float4*>(s);
    #pragma unroll 5
    for (int j = tid; j < NV; j += THREADS) {
        __stcs(dst + j, ss[j]);
    }
}

extern "C" void kernel_launch(void* const* d_in, const int* in_sizes, int n_in,
                              void* d_out, int out_size) {
    const float* x = (const float*)d_in[0];
    float* out = (float*)d_out;
    const int blocks = out_size / (TILE * NE);   // 9984
    det_decode_kernel<<<blocks, THREADS>>>(x, out);
}